// round 6
// baseline (speedup 1.0000x reference)
#include <cuda_runtime.h>
#include <math.h>
#include <stdint.h>

#define BATCH 2
#define SEQ   2048
#define EMB   1024
#define NHEAD 16
#define HDIM  64
#define MTOT  (BATCH*SEQ)   // 4096

// Scratch (allocation-free contract: __device__ globals)
__device__ float g_q[BATCH*NHEAD*SEQ*HDIM];   // [b][h][s][d]
__device__ float g_k[BATCH*NHEAD*SEQ*HDIM];
__device__ float g_v[BATCH*NHEAD*SEQ*HDIM];
__device__ float g_ctx[(size_t)MTOT*EMB];     // [b*s][e]

// ===========================================================================
// Portable tensor-core path: mma.sync m16n8k8 tf32 (sm_80+ PTX; compiles to
// legacy HMMA on sm_103 — tcgen05 is unreachable because the harness builds
// compute_103 PTX, not compute_103a).
// ===========================================================================
__device__ __forceinline__ uint32_t f2tf32(float x) {
    uint32_t u;
    asm("cvt.rna.tf32.f32 %0, %1;" : "=r"(u) : "f"(x));
    return u;
}

__device__ __forceinline__ void mma8(float* d, const uint32_t* a, const uint32_t* b) {
    asm volatile(
        "mma.sync.aligned.m16n8k8.row.col.f32.tf32.tf32.f32 "
        "{%0,%1,%2,%3}, {%4,%5,%6,%7}, {%8,%9}, {%0,%1,%2,%3};"
        : "+f"(d[0]), "+f"(d[1]), "+f"(d[2]), "+f"(d[3])
        : "r"(a[0]), "r"(a[1]), "r"(a[2]), "r"(a[3]), "r"(b[0]), "r"(b[1]));
}

// Split a float4 into tf32 (hi,lo) pairs and store in fragment order:
// p[0..3] = (hi_j, lo_j) for j = 0..3 (two float4 stores, 16B aligned).
__device__ __forceinline__ void split_store(float2* p, float4 g) {
    float h0 = __uint_as_float(f2tf32(g.x)); float l0 = __uint_as_float(f2tf32(g.x - h0));
    float h1 = __uint_as_float(f2tf32(g.y)); float l1 = __uint_as_float(f2tf32(g.y - h1));
    float h2 = __uint_as_float(f2tf32(g.z)); float l2 = __uint_as_float(f2tf32(g.z - h2));
    float h3 = __uint_as_float(f2tf32(g.w)); float l3 = __uint_as_float(f2tf32(g.w - h3));
    *(float4*)(p)     = make_float4(h0, l0, h1, l1);
    *(float4*)(p + 2) = make_float4(h2, l2, h3, l3);
}

// ===========================================================================
// 3xTF32 mma.sync GEMM: C[M,N] = A[M,K] @ W[N,K]^T, near-fp32 accuracy.
// CTA tile 128x128, BK=32. 8 warps: warp (wm=wid&1, wn=wid>>1) owns a
// 64m x 32n warp tile = 4x4 m16n8 mma tiles, 3 passes (hh, hl, lh).
// Smem is FRAGMENT-MAJOR with interleaved (hi,lo) float2 elements:
//   sA[kk 0..3][mt 0..7][aidx 0..3][lane 0..31]  (32 KB)
//   sB[kk 0..3][nt 0..15][bidx 0..1][lane 0..31] (32 KB)
// so mainloop LDS.64 are conflict-free and the fill is STS.128.
// Fragment mapping (CUTLASS SM80_16x8x8_F32TF32TF32F32_TN):
//   A: a0=(gr,tg) a1=(gr+8,tg) a2=(gr,tg+4) a3=(gr+8,tg+4)
//   B: b0=(n=gr,k=tg) b1=(gr,tg+4)
//   D: d0=(gr,2tg) d1=(gr,2tg+1) d2=(gr+8,2tg) d3=(gr+8,2tg+1)
// Global slab (it+1) is prefetched into registers before the mma block.
// EPI==0: scatter to g_q/g_k/g_v.  EPI==1: A=g_ctx, out = C + bias.
// ===========================================================================
#define GEMM_SMEM_BYTES 65536

template<int EPI>
__global__ __launch_bounds__(256) void mma_gemm_kernel(
    const float* __restrict__ Ain,
    const float* __restrict__ W,
    const float* __restrict__ bias,
    float* __restrict__ out,
    int K, int Nfull)
{
    extern __shared__ char dsmem[];
    float2* sA = (float2*)dsmem;              // 32 KB
    float2* sB = (float2*)(dsmem + 32768);    // 32 KB

    const float* A = (EPI == 1) ? (const float*)g_ctx : Ain;

    const int tid  = threadIdx.x;
    const int wid  = tid >> 5;
    const int lane = tid & 31;
    const int wm   = wid & 1;
    const int wn   = wid >> 1;
    const int gr   = lane >> 2;
    const int tg   = lane & 3;
    const int m0   = blockIdx.y * 128;
    const int n0   = blockIdx.x * 128;

    // ---- per-thread fill slots: 4 float4 loads each for A and B ----
    const float *pA[4], *pB[4];
    int offA[4], offB[4];     // float2 indices into sA / sB
    #pragma unroll
    for (int t = 0; t < 4; t++) {
        int idx = tid + t * 256;     // 0..1023
        int row = idx >> 3;          // 0..127
        int c4  = idx & 7;           // 16B column within BK=32
        pA[t] = A + (size_t)(m0 + row) * K + c4 * 4;
        pB[t] = W + (size_t)(n0 + row) * K + c4 * 4;
        int kk   = c4 >> 1;
        int mt   = row >> 4;
        int aidx = ((row >> 3) & 1) | ((c4 & 1) << 1);
        offA[t]  = (((kk*8 + mt)*4 + aidx) << 5) + (row & 7) * 4;
        int nt   = row >> 3;
        int bidx = c4 & 1;
        offB[t]  = (((kk*16 + nt)*2 + bidx) << 5) + (row & 7) * 4;
    }

    float acc[4][4][4];
    #pragma unroll
    for (int i = 0; i < 4; i++)
        #pragma unroll
        for (int j = 0; j < 4; j++)
            #pragma unroll
            for (int v = 0; v < 4; v++) acc[i][j][v] = 0.f;

    // prefetch slab 0
    float4 gA[4], gB[4];
    #pragma unroll
    for (int t = 0; t < 4; t++) {
        gA[t] = *(const float4*)(pA[t]);
        gB[t] = *(const float4*)(pB[t]);
    }

    const int niter = K >> 5;   // BK = 32
    for (int it = 0; it < niter; it++) {
        // ---- fill smem (tf32 split, fragment-major) ----
        #pragma unroll
        for (int t = 0; t < 4; t++) {
            split_store(sA + offA[t], gA[t]);
            split_store(sB + offB[t], gB[t]);
        }
        __syncthreads();

        // ---- prefetch next slab (latency hidden behind mma) ----
        if (it + 1 < niter) {
            const int ko = (it + 1) << 5;
            #pragma unroll
            for (int t = 0; t < 4; t++) {
                gA[t] = *(const float4*)(pA[t] + ko);
                gB[t] = *(const float4*)(pB[t] + ko);
            }
        }

        // ---- mma over the 4 k8-steps of this slab ----
        #pragma unroll
        for (int kk = 0; kk < 4; kk++) {
            uint32_t ah[4][4], al[4][4], bh[4][2], bl[4][2];
            #pragma unroll
            for (int mt4 = 0; mt4 < 4; mt4++) {
                int mt = wm*4 + mt4;
                #pragma unroll
                for (int ai = 0; ai < 4; ai++) {
                    float2 v = sA[(((kk*8 + mt)*4 + ai) << 5) + lane];
                    ah[mt4][ai] = __float_as_uint(v.x);
                    al[mt4][ai] = __float_as_uint(v.y);
                }
            }
            #pragma unroll
            for (int nt4 = 0; nt4 < 4; nt4++) {
                int nt = wn*4 + nt4;
                #pragma unroll
                for (int bi = 0; bi < 2; bi++) {
                    float2 v = sB[(((kk*16 + nt)*2 + bi) << 5) + lane];
                    bh[nt4][bi] = __float_as_uint(v.x);
                    bl[nt4][bi] = __float_as_uint(v.y);
                }
            }
            // 3 passes; 16 independent mmas per pass (no RAW chains back-to-back)
            #pragma unroll
            for (int mt4 = 0; mt4 < 4; mt4++)
                #pragma unroll
                for (int nt4 = 0; nt4 < 4; nt4++)
                    mma8(acc[mt4][nt4], ah[mt4], bh[nt4]);
            #pragma unroll
            for (int mt4 = 0; mt4 < 4; mt4++)
                #pragma unroll
                for (int nt4 = 0; nt4 < 4; nt4++)
                    mma8(acc[mt4][nt4], ah[mt4], bl[nt4]);
            #pragma unroll
            for (int mt4 = 0; mt4 < 4; mt4++)
                #pragma unroll
                for (int nt4 = 0; nt4 < 4; nt4++)
                    mma8(acc[mt4][nt4], al[mt4], bh[nt4]);
        }
        __syncthreads();
    }

    // ---- epilogue ----
    #pragma unroll
    for (int mt4 = 0; mt4 < 4; mt4++) {
        const int mlo = m0 + wm*64 + mt4*16 + gr;
        const int mhi = mlo + 8;
        #pragma unroll
        for (int nt4 = 0; nt4 < 4; nt4++) {
            const int nn = n0 + wn*32 + nt4*8 + tg*2;
            const float* d = acc[mt4][nt4];
            if (EPI == 0) {
                const int which = n0 >> 10;
                float* dst = (which == 0) ? g_q : ((which == 1) ? g_k : g_v);
                const int nl = nn & 1023;
                const int h  = nl >> 6;
                const int dd = nl & (HDIM - 1);
                {
                    int b = mlo >> 11, s = mlo & (SEQ - 1);
                    *(float2*)&dst[(((b*NHEAD + h)*SEQ) + s)*HDIM + dd] =
                        make_float2(d[0], d[1]);
                }
                {
                    int b = mhi >> 11, s = mhi & (SEQ - 1);
                    *(float2*)&dst[(((b*NHEAD + h)*SEQ) + s)*HDIM + dd] =
                        make_float2(d[2], d[3]);
                }
            } else {
                float2 bv = *(const float2*)&bias[nn];
                *(float2*)&out[(size_t)mlo * Nfull + nn] =
                    make_float2(d[0] + bv.x, d[1] + bv.y);
                *(float2*)&out[(size_t)mhi * Nfull + nn] =
                    make_float2(d[2] + bv.x, d[3] + bv.y);
            }
        }
    }
}

// ---------------------------------------------------------------------------
// Causal flash attention, fp32, D=64, register-blocked (unchanged from R3:
// measured ~640us; 4x4 micro-tile, 16 FMA per 8 LDS).
// ---------------------------------------------------------------------------
__global__ __launch_bounds__(256) void flash_kernel()
{
    __shared__ __align__(16) float Qs[64][65];
    __shared__ __align__(16) float Ks[64][65];
    __shared__ __align__(16) float Vs[64][68];
    __shared__ __align__(16) float Ps[64][68];

    const int qt = blockIdx.x;
    const int h  = blockIdx.y;
    const int b  = blockIdx.z;
    const int bh = b*NHEAD + h;
    const float* Qg = g_q + (size_t)bh * SEQ * HDIM;
    const float* Kg = g_k + (size_t)bh * SEQ * HDIM;
    const float* Vg = g_v + (size_t)bh * SEQ * HDIM;

    const int tid = threadIdx.x;
    const int ty  = tid >> 4;
    const int tx  = tid & 15;
    const int r0  = ty * 4;
    const int c0  = tx * 4;
    const int q0  = qt * 64;

    for (int i = tid; i < 64*16; i += 256) {
        int rr = i >> 4, ff = (i & 15) << 2;
        float4 v = *(const float4*)(Qg + (size_t)(q0 + rr)*HDIM + ff);
        Qs[rr][ff+0] = v.x*8.f; Qs[rr][ff+1] = v.y*8.f;
        Qs[rr][ff+2] = v.z*8.f; Qs[rr][ff+3] = v.w*8.f;
    }

    float m[4], l[4], acc[4][4];
    #pragma unroll
    for (int i = 0; i < 4; i++) {
        m[i] = -1e30f; l[i] = 0.f;
        #pragma unroll
        for (int j = 0; j < 4; j++) acc[i][j] = 0.f;
    }

    for (int kt = 0; kt <= qt; kt++) {
        __syncthreads();
        for (int i = tid; i < 64*16; i += 256) {
            int rr = i >> 4, ff = (i & 15) << 2;
            float4 kv = *(const float4*)(Kg + (size_t)(kt*64 + rr)*HDIM + ff);
            float4 vv = *(const float4*)(Vg + (size_t)(kt*64 + rr)*HDIM + ff);
            Ks[rr][ff+0] = kv.x; Ks[rr][ff+1] = kv.y;
            Ks[rr][ff+2] = kv.z; Ks[rr][ff+3] = kv.w;
            *(float4*)&Vs[rr][ff] = vv;
        }
        __syncthreads();

        float s[4][4];
        #pragma unroll
        for (int i = 0; i < 4; i++)
            #pragma unroll
            for (int j = 0; j < 4; j++) s[i][j] = 0.f;

        #pragma unroll 8
        for (int d = 0; d < 64; d++) {
            float qf[4], kf[4];
            #pragma unroll
            for (int i = 0; i < 4; i++) qf[i] = Qs[r0+i][d];
            #pragma unroll
            for (int j = 0; j < 4; j++) kf[j] = Ks[c0+j][d];
            #pragma unroll
            for (int i = 0; i < 4; i++)
                #pragma unroll
                for (int j = 0; j < 4; j++)
                    s[i][j] = fmaf(qf[i], kf[j], s[i][j]);
        }

        if (kt == qt) {
            #pragma unroll
            for (int i = 0; i < 4; i++)
                #pragma unroll
                for (int j = 0; j < 4; j++)
                    if (c0 + j > r0 + i) s[i][j] = -1e30f;
        }

        float mnew[4], rsum[4];
        #pragma unroll
        for (int i = 0; i < 4; i++) {
            float mloc = fmaxf(fmaxf(s[i][0], s[i][1]), fmaxf(s[i][2], s[i][3]));
            mloc = fmaxf(mloc, __shfl_xor_sync(0xffffffffu, mloc, 1));
            mloc = fmaxf(mloc, __shfl_xor_sync(0xffffffffu, mloc, 2));
            mloc = fmaxf(mloc, __shfl_xor_sync(0xffffffffu, mloc, 4));
            mloc = fmaxf(mloc, __shfl_xor_sync(0xffffffffu, mloc, 8));
            mnew[i] = fmaxf(m[i], mloc);
        }
        #pragma unroll
        for (int i = 0; i < 4; i++) {
            float rs = 0.f;
            #pragma unroll
            for (int j = 0; j < 4; j++) {
                float e = __expf(s[i][j] - mnew[i]);
                s[i][j] = e;
                rs += e;
            }
            rs += __shfl_xor_sync(0xffffffffu, rs, 1);
            rs += __shfl_xor_sync(0xffffffffu, rs, 2);
            rs += __shfl_xor_sync(0xffffffffu, rs, 4);
            rs += __shfl_xor_sync(0xffffffffu, rs, 8);
            rsum[i] = rs;
        }
        #pragma unroll
        for (int i = 0; i < 4; i++) {
            float alpha = __expf(m[i] - mnew[i]);
            m[i] = mnew[i];
            l[i] = l[i] * alpha + rsum[i];
            #pragma unroll
            for (int j = 0; j < 4; j++) acc[i][j] *= alpha;
            *(float4*)&Ps[r0+i][c0] = make_float4(s[i][0], s[i][1], s[i][2], s[i][3]);
        }
        __syncthreads();

        #pragma unroll 8
        for (int k = 0; k < 64; k++) {
            float pf[4];
            #pragma unroll
            for (int i = 0; i < 4; i++) pf[i] = Ps[r0+i][k];
            float4 v = *(const float4*)&Vs[k][c0];
            #pragma unroll
            for (int i = 0; i < 4; i++) {
                acc[i][0] = fmaf(pf[i], v.x, acc[i][0]);
                acc[i][1] = fmaf(pf[i], v.y, acc[i][1]);
                acc[i][2] = fmaf(pf[i], v.z, acc[i][2]);
                acc[i][3] = fmaf(pf[i], v.w, acc[i][3]);
            }
        }
    }

    #pragma unroll
    for (int i = 0; i < 4; i++) {
        float inv = 1.0f / l[i];
        float* outp = g_ctx + ((size_t)(b*SEQ + q0 + r0 + i)) * EMB + h*HDIM + c0;
        *(float4*)outp = make_float4(acc[i][0]*inv, acc[i][1]*inv,
                                     acc[i][2]*inv, acc[i][3]*inv);
    }
}

// ---------------------------------------------------------------------------
// Inputs (metadata order): x [2,2048,1024] f32, w_qkv [3072,1024] f32,
// w_proj [1024,1024] f32, b_proj [1024] f32. Output: [2,2048,1024] f32.
// ---------------------------------------------------------------------------
extern "C" void kernel_launch(void* const* d_in, const int* in_sizes, int n_in,
                              void* d_out, int out_size)
{
    (void)in_sizes; (void)n_in; (void)out_size;
    const float* x      = (const float*)d_in[0];
    const float* w_qkv  = (const float*)d_in[1];
    const float* w_proj = (const float*)d_in[2];
    const float* b_proj = (const float*)d_in[3];
    float* out = (float*)d_out;

    cudaFuncSetAttribute(mma_gemm_kernel<0>,
                         cudaFuncAttributeMaxDynamicSharedMemorySize, GEMM_SMEM_BYTES);
    cudaFuncSetAttribute(mma_gemm_kernel<1>,
                         cudaFuncAttributeMaxDynamicSharedMemorySize, GEMM_SMEM_BYTES);

    // 1) QKV GEMM (3xTF32 mma.sync): [4096,1024] @ [3072,1024]^T -> g_q/g_k/g_v
    dim3 g1((3*EMB)/128, MTOT/128);
    mma_gemm_kernel<0><<<g1, 256, GEMM_SMEM_BYTES>>>(x, w_qkv, nullptr, nullptr,
                                                     EMB, 3*EMB);

    // 2) Causal flash attention -> g_ctx
    dim3 g2(SEQ/64, NHEAD, BATCH);
    flash_kernel<<<g2, 256>>>();

    // 3) Proj GEMM + bias (3xTF32 mma.sync): g_ctx @ w_proj^T + b_proj -> out
    dim3 g3(EMB/128, MTOT/128);
    mma_gemm_kernel<1><<<g3, 256, GEMM_SMEM_BYTES>>>(nullptr, w_proj, b_proj, out,
                                                     EMB, EMB);
}

// round 7
// speedup vs baseline: 1.0247x; 1.0247x over previous
#include <cuda_runtime.h>
#include <math.h>
#include <stdint.h>

#define BATCH 2
#define SEQ   2048
#define EMB   1024
#define NHEAD 16
#define HDIM  64
#define MTOT  (BATCH*SEQ)   // 4096

// Scratch (allocation-free contract: __device__ globals)
__device__ float g_q[BATCH*NHEAD*SEQ*HDIM];   // [b][h][s][d]
__device__ float g_k[BATCH*NHEAD*SEQ*HDIM];
__device__ float g_v[BATCH*NHEAD*SEQ*HDIM];
__device__ float g_ctx[(size_t)MTOT*EMB];     // [b*s][e]

// ===========================================================================
// Portable tensor-core path: mma.sync m16n8k8 tf32 (sm_80+ PTX; tcgen05 is
// unreachable — harness builds compute_103 PTX, not compute_103a).
// ===========================================================================
__device__ __forceinline__ uint32_t f2tf32(float x) {
    uint32_t u;
    asm("cvt.rna.tf32.f32 %0, %1;" : "=r"(u) : "f"(x));
    return u;
}

__device__ __forceinline__ void mma8(float* d, const uint32_t* a, const uint32_t* b) {
    asm volatile(
        "mma.sync.aligned.m16n8k8.row.col.f32.tf32.tf32.f32 "
        "{%0,%1,%2,%3}, {%4,%5,%6,%7}, {%8,%9}, {%0,%1,%2,%3};"
        : "+f"(d[0]), "+f"(d[1]), "+f"(d[2]), "+f"(d[3])
        : "r"(a[0]), "r"(a[1]), "r"(a[2]), "r"(a[3]), "r"(b[0]), "r"(b[1]));
}

// Split a float4 into tf32 (hi,lo) pairs, store in fragment order (2x STS.128).
__device__ __forceinline__ void split_store(float2* p, float4 g) {
    float h0 = __uint_as_float(f2tf32(g.x)); float l0 = g.x - h0;
    float h1 = __uint_as_float(f2tf32(g.y)); float l1 = g.y - h1;
    float h2 = __uint_as_float(f2tf32(g.z)); float l2 = g.z - h2;
    float h3 = __uint_as_float(f2tf32(g.w)); float l3 = g.w - h3;
    *(float4*)(p)     = make_float4(h0, l0, h1, l1);
    *(float4*)(p + 2) = make_float4(h2, l2, h3, l3);
}

// ===========================================================================
// 3xTF32 mma.sync GEMM, DOUBLE-BUFFERED: C[M,N] = A[M,K] @ W[N,K]^T.
// CTA tile 128x128, BK=32, 8 warps (64m x 32n warp tile, 4x4 mma tiles,
// 3 passes hh/hl/lh). Smem: two 64KB stages (fragment-major, interleaved
// (hi,lo) float2). Per iteration: LDG prefetch slab it+1 -> MMA on stage
// it&1 -> split/STS into stage (it+1)&1 -> one __syncthreads. The fill is
// issue-slot work hidden under the MMA block (R5 profile: tensor=26.7%
// because the single-buffered fill was a serial phase).
// Fragment mapping (CUTLASS SM80_16x8x8_F32TF32TF32F32_TN) — verified R5.
// EPI==0: scatter to g_q/g_k/g_v.  EPI==1: A=g_ctx, out = C + bias.
// ===========================================================================
#define GEMM_STAGE_BYTES 65536
#define GEMM_SMEM_BYTES  (2*GEMM_STAGE_BYTES)   // 128 KB

template<int EPI>
__global__ __launch_bounds__(256) void mma_gemm_kernel(
    const float* __restrict__ Ain,
    const float* __restrict__ W,
    const float* __restrict__ bias,
    float* __restrict__ out,
    int K, int Nfull)
{
    extern __shared__ char dsmem[];
    const float* A = (EPI == 1) ? (const float*)g_ctx : Ain;

    const int tid  = threadIdx.x;
    const int wid  = tid >> 5;
    const int lane = tid & 31;
    const int wm   = wid & 1;
    const int wn   = wid >> 1;
    const int gr   = lane >> 2;
    const int tg   = lane & 3;
    const int m0   = blockIdx.y * 128;
    const int n0   = blockIdx.x * 128;

    // ---- per-thread fill slots: 4 float4 loads each for A and B ----
    const float *pA[4], *pB[4];
    int offA[4], offB[4];     // float2 indices within a stage
    #pragma unroll
    for (int t = 0; t < 4; t++) {
        int idx = tid + t * 256;     // 0..1023
        int row = idx >> 3;          // 0..127
        int c4  = idx & 7;           // 16B column within BK=32
        pA[t] = A + (size_t)(m0 + row) * K + c4 * 4;
        pB[t] = W + (size_t)(n0 + row) * K + c4 * 4;
        int kk   = c4 >> 1;
        int mt   = row >> 4;
        int aidx = ((row >> 3) & 1) | ((c4 & 1) << 1);
        offA[t]  = (((kk*8 + mt)*4 + aidx) << 5) + (row & 7) * 4;
        int nt   = row >> 3;
        int bidx = c4 & 1;
        offB[t]  = (((kk*16 + nt)*2 + bidx) << 5) + (row & 7) * 4;
    }

    float acc[4][4][4];
    #pragma unroll
    for (int i = 0; i < 4; i++)
        #pragma unroll
        for (int j = 0; j < 4; j++)
            #pragma unroll
            for (int v = 0; v < 4; v++) acc[i][j][v] = 0.f;

    // ---- prologue: load + fill stage 0 ----
    float4 gA[4], gB[4];
    #pragma unroll
    for (int t = 0; t < 4; t++) {
        gA[t] = *(const float4*)(pA[t]);
        gB[t] = *(const float4*)(pB[t]);
    }
    {
        float2* sA0 = (float2*)(dsmem);
        float2* sB0 = (float2*)(dsmem + 32768);
        #pragma unroll
        for (int t = 0; t < 4; t++) {
            split_store(sA0 + offA[t], gA[t]);
            split_store(sB0 + offB[t], gB[t]);
        }
    }
    __syncthreads();

    const int niter = K >> 5;   // BK = 32
    for (int it = 0; it < niter; it++) {
        const int p = it & 1;
        float2* cA = (float2*)(dsmem + p*GEMM_STAGE_BYTES);
        float2* cB = (float2*)(dsmem + p*GEMM_STAGE_BYTES + 32768);
        const bool more = (it + 1 < niter);

        // prefetch next slab into registers (covered by the MMA block below)
        if (more) {
            const int ko = (it + 1) << 5;
            #pragma unroll
            for (int t = 0; t < 4; t++) {
                gA[t] = *(const float4*)(pA[t] + ko);
                gB[t] = *(const float4*)(pB[t] + ko);
            }
        }

        // ---- mma over the 4 k8-steps of this stage ----
        #pragma unroll
        for (int kk = 0; kk < 4; kk++) {
            uint32_t ah[4][4], al[4][4], bh[4][2], bl[4][2];
            #pragma unroll
            for (int mt4 = 0; mt4 < 4; mt4++) {
                int mt = wm*4 + mt4;
                #pragma unroll
                for (int ai = 0; ai < 4; ai++) {
                    float2 v = cA[(((kk*8 + mt)*4 + ai) << 5) + lane];
                    ah[mt4][ai] = __float_as_uint(v.x);
                    al[mt4][ai] = __float_as_uint(v.y);
                }
            }
            #pragma unroll
            for (int nt4 = 0; nt4 < 4; nt4++) {
                int nt = wn*4 + nt4;
                #pragma unroll
                for (int bi = 0; bi < 2; bi++) {
                    float2 v = cB[(((kk*16 + nt)*2 + bi) << 5) + lane];
                    bh[nt4][bi] = __float_as_uint(v.x);
                    bl[nt4][bi] = __float_as_uint(v.y);
                }
            }
            // 3 passes; 16 independent mmas per pass
            #pragma unroll
            for (int mt4 = 0; mt4 < 4; mt4++)
                #pragma unroll
                for (int nt4 = 0; nt4 < 4; nt4++)
                    mma8(acc[mt4][nt4], ah[mt4], bh[nt4]);
            #pragma unroll
            for (int mt4 = 0; mt4 < 4; mt4++)
                #pragma unroll
                for (int nt4 = 0; nt4 < 4; nt4++)
                    mma8(acc[mt4][nt4], ah[mt4], bl[nt4]);
            #pragma unroll
            for (int mt4 = 0; mt4 < 4; mt4++)
                #pragma unroll
                for (int nt4 = 0; nt4 < 4; nt4++)
                    mma8(acc[mt4][nt4], al[mt4], bh[nt4]);
        }

        // ---- fill the other stage (read by mma at it+1) ----
        if (more) {
            float2* nA = (float2*)(dsmem + (p^1)*GEMM_STAGE_BYTES);
            float2* nB = (float2*)(dsmem + (p^1)*GEMM_STAGE_BYTES + 32768);
            #pragma unroll
            for (int t = 0; t < 4; t++) {
                split_store(nA + offA[t], gA[t]);
                split_store(nB + offB[t], gB[t]);
            }
        }
        __syncthreads();
    }

    // ---- epilogue ----
    #pragma unroll
    for (int mt4 = 0; mt4 < 4; mt4++) {
        const int mlo = m0 + wm*64 + mt4*16 + gr;
        const int mhi = mlo + 8;
        #pragma unroll
        for (int nt4 = 0; nt4 < 4; nt4++) {
            const int nn = n0 + wn*32 + nt4*8 + tg*2;
            const float* d = acc[mt4][nt4];
            if (EPI == 0) {
                const int which = n0 >> 10;
                float* dst = (which == 0) ? g_q : ((which == 1) ? g_k : g_v);
                const int nl = nn & 1023;
                const int h  = nl >> 6;
                const int dd = nl & (HDIM - 1);
                {
                    int b = mlo >> 11, s = mlo & (SEQ - 1);
                    *(float2*)&dst[(((b*NHEAD + h)*SEQ) + s)*HDIM + dd] =
                        make_float2(d[0], d[1]);
                }
                {
                    int b = mhi >> 11, s = mhi & (SEQ - 1);
                    *(float2*)&dst[(((b*NHEAD + h)*SEQ) + s)*HDIM + dd] =
                        make_float2(d[2], d[3]);
                }
            } else {
                float2 bv = *(const float2*)&bias[nn];
                *(float2*)&out[(size_t)mlo * Nfull + nn] =
                    make_float2(d[0] + bv.x, d[1] + bv.y);
                *(float2*)&out[(size_t)mhi * Nfull + nn] =
                    make_float2(d[2] + bv.x, d[3] + bv.y);
            }
        }
    }
}

// ---------------------------------------------------------------------------
// Causal flash attention, fp32, D=64, register-blocked (unchanged from R3:
// measured ~640us; 4x4 micro-tile, 16 FMA per 8 LDS).
// ---------------------------------------------------------------------------
__global__ __launch_bounds__(256) void flash_kernel()
{
    __shared__ __align__(16) float Qs[64][65];
    __shared__ __align__(16) float Ks[64][65];
    __shared__ __align__(16) float Vs[64][68];
    __shared__ __align__(16) float Ps[64][68];

    const int qt = blockIdx.x;
    const int h  = blockIdx.y;
    const int b  = blockIdx.z;
    const int bh = b*NHEAD + h;
    const float* Qg = g_q + (size_t)bh * SEQ * HDIM;
    const float* Kg = g_k + (size_t)bh * SEQ * HDIM;
    const float* Vg = g_v + (size_t)bh * SEQ * HDIM;

    const int tid = threadIdx.x;
    const int ty  = tid >> 4;
    const int tx  = tid & 15;
    const int r0  = ty * 4;
    const int c0  = tx * 4;
    const int q0  = qt * 64;

    for (int i = tid; i < 64*16; i += 256) {
        int rr = i >> 4, ff = (i & 15) << 2;
        float4 v = *(const float4*)(Qg + (size_t)(q0 + rr)*HDIM + ff);
        Qs[rr][ff+0] = v.x*8.f; Qs[rr][ff+1] = v.y*8.f;
        Qs[rr][ff+2] = v.z*8.f; Qs[rr][ff+3] = v.w*8.f;
    }

    float m[4], l[4], acc[4][4];
    #pragma unroll
    for (int i = 0; i < 4; i++) {
        m[i] = -1e30f; l[i] = 0.f;
        #pragma unroll
        for (int j = 0; j < 4; j++) acc[i][j] = 0.f;
    }

    for (int kt = 0; kt <= qt; kt++) {
        __syncthreads();
        for (int i = tid; i < 64*16; i += 256) {
            int rr = i >> 4, ff = (i & 15) << 2;
            float4 kv = *(const float4*)(Kg + (size_t)(kt*64 + rr)*HDIM + ff);
            float4 vv = *(const float4*)(Vg + (size_t)(kt*64 + rr)*HDIM + ff);
            Ks[rr][ff+0] = kv.x; Ks[rr][ff+1] = kv.y;
            Ks[rr][ff+2] = kv.z; Ks[rr][ff+3] = kv.w;
            *(float4*)&Vs[rr][ff] = vv;
        }
        __syncthreads();

        float s[4][4];
        #pragma unroll
        for (int i = 0; i < 4; i++)
            #pragma unroll
            for (int j = 0; j < 4; j++) s[i][j] = 0.f;

        #pragma unroll 8
        for (int d = 0; d < 64; d++) {
            float qf[4], kf[4];
            #pragma unroll
            for (int i = 0; i < 4; i++) qf[i] = Qs[r0+i][d];
            #pragma unroll
            for (int j = 0; j < 4; j++) kf[j] = Ks[c0+j][d];
            #pragma unroll
            for (int i = 0; i < 4; i++)
                #pragma unroll
                for (int j = 0; j < 4; j++)
                    s[i][j] = fmaf(qf[i], kf[j], s[i][j]);
        }

        if (kt == qt) {
            #pragma unroll
            for (int i = 0; i < 4; i++)
                #pragma unroll
                for (int j = 0; j < 4; j++)
                    if (c0 + j > r0 + i) s[i][j] = -1e30f;
        }

        float mnew[4], rsum[4];
        #pragma unroll
        for (int i = 0; i < 4; i++) {
            float mloc = fmaxf(fmaxf(s[i][0], s[i][1]), fmaxf(s[i][2], s[i][3]));
            mloc = fmaxf(mloc, __shfl_xor_sync(0xffffffffu, mloc, 1));
            mloc = fmaxf(mloc, __shfl_xor_sync(0xffffffffu, mloc, 2));
            mloc = fmaxf(mloc, __shfl_xor_sync(0xffffffffu, mloc, 4));
            mloc = fmaxf(mloc, __shfl_xor_sync(0xffffffffu, mloc, 8));
            mnew[i] = fmaxf(m[i], mloc);
        }
        #pragma unroll
        for (int i = 0; i < 4; i++) {
            float rs = 0.f;
            #pragma unroll
            for (int j = 0; j < 4; j++) {
                float e = __expf(s[i][j] - mnew[i]);
                s[i][j] = e;
                rs += e;
            }
            rs += __shfl_xor_sync(0xffffffffu, rs, 1);
            rs += __shfl_xor_sync(0xffffffffu, rs, 2);
            rs += __shfl_xor_sync(0xffffffffu, rs, 4);
            rs += __shfl_xor_sync(0xffffffffu, rs, 8);
            rsum[i] = rs;
        }
        #pragma unroll
        for (int i = 0; i < 4; i++) {
            float alpha = __expf(m[i] - mnew[i]);
            m[i] = mnew[i];
            l[i] = l[i] * alpha + rsum[i];
            #pragma unroll
            for (int j = 0; j < 4; j++) acc[i][j] *= alpha;
            *(float4*)&Ps[r0+i][c0] = make_float4(s[i][0], s[i][1], s[i][2], s[i][3]);
        }
        __syncthreads();

        #pragma unroll 8
        for (int k = 0; k < 64; k++) {
            float pf[4];
            #pragma unroll
            for (int i = 0; i < 4; i++) pf[i] = Ps[r0+i][k];
            float4 v = *(const float4*)&Vs[k][c0];
            #pragma unroll
            for (int i = 0; i < 4; i++) {
                acc[i][0] = fmaf(pf[i], v.x, acc[i][0]);
                acc[i][1] = fmaf(pf[i], v.y, acc[i][1]);
                acc[i][2] = fmaf(pf[i], v.z, acc[i][2]);
                acc[i][3] = fmaf(pf[i], v.w, acc[i][3]);
            }
        }
    }

    #pragma unroll
    for (int i = 0; i < 4; i++) {
        float inv = 1.0f / l[i];
        float* outp = g_ctx + ((size_t)(b*SEQ + q0 + r0 + i)) * EMB + h*HDIM + c0;
        *(float4*)outp = make_float4(acc[i][0]*inv, acc[i][1]*inv,
                                     acc[i][2]*inv, acc[i][3]*inv);
    }
}

// ---------------------------------------------------------------------------
// Inputs (metadata order): x [2,2048,1024] f32, w_qkv [3072,1024] f32,
// w_proj [1024,1024] f32, b_proj [1024] f32. Output: [2,2048,1024] f32.
// ---------------------------------------------------------------------------
extern "C" void kernel_launch(void* const* d_in, const int* in_sizes, int n_in,
                              void* d_out, int out_size)
{
    (void)in_sizes; (void)n_in; (void)out_size;
    const float* x      = (const float*)d_in[0];
    const float* w_qkv  = (const float*)d_in[1];
    const float* w_proj = (const float*)d_in[2];
    const float* b_proj = (const float*)d_in[3];
    float* out = (float*)d_out;

    cudaFuncSetAttribute(mma_gemm_kernel<0>,
                         cudaFuncAttributeMaxDynamicSharedMemorySize, GEMM_SMEM_BYTES);
    cudaFuncSetAttribute(mma_gemm_kernel<1>,
                         cudaFuncAttributeMaxDynamicSharedMemorySize, GEMM_SMEM_BYTES);

    // 1) QKV GEMM (3xTF32 mma.sync): [4096,1024] @ [3072,1024]^T -> g_q/g_k/g_v
    dim3 g1((3*EMB)/128, MTOT/128);
    mma_gemm_kernel<0><<<g1, 256, GEMM_SMEM_BYTES>>>(x, w_qkv, nullptr, nullptr,
                                                     EMB, 3*EMB);

    // 2) Causal flash attention -> g_ctx
    dim3 g2(SEQ/64, NHEAD, BATCH);
    flash_kernel<<<g2, 256>>>();

    // 3) Proj GEMM + bias (3xTF32 mma.sync): g_ctx @ w_proj^T + b_proj -> out
    dim3 g3(EMB/128, MTOT/128);
    mma_gemm_kernel<1><<<g3, 256, GEMM_SMEM_BYTES>>>(nullptr, w_proj, b_proj, out,
                                                     EMB, EMB);
}

// round 8
// speedup vs baseline: 1.0614x; 1.0359x over previous
#include <cuda_runtime.h>
#include <math.h>
#include <stdint.h>

#define BATCH 2
#define SEQ   2048
#define EMB   1024
#define NHEAD 16
#define HDIM  64
#define MTOT  (BATCH*SEQ)   // 4096

// Scratch (allocation-free contract: __device__ globals)
__device__ float g_q[BATCH*NHEAD*SEQ*HDIM];   // [b][h][s][d]
__device__ float g_k[BATCH*NHEAD*SEQ*HDIM];
__device__ float g_v[BATCH*NHEAD*SEQ*HDIM];
__device__ float g_ctx[(size_t)MTOT*EMB];     // [b*s][e]

// ===========================================================================
// Portable tensor-core path: mma.sync m16n8k8 tf32 (sm_80+ PTX; tcgen05 is
// unreachable — harness builds compute_103 PTX, not compute_103a).
// ===========================================================================
__device__ __forceinline__ uint32_t f2tf32(float x) {
    uint32_t u;
    asm("cvt.rna.tf32.f32 %0, %1;" : "=r"(u) : "f"(x));
    return u;
}

__device__ __forceinline__ void mma8(float* d, const uint32_t* a, const uint32_t* b) {
    asm volatile(
        "mma.sync.aligned.m16n8k8.row.col.f32.tf32.tf32.f32 "
        "{%0,%1,%2,%3}, {%4,%5,%6,%7}, {%8,%9}, {%0,%1,%2,%3};"
        : "+f"(d[0]), "+f"(d[1]), "+f"(d[2]), "+f"(d[3])
        : "r"(a[0]), "r"(a[1]), "r"(a[2]), "r"(a[3]), "r"(b[0]), "r"(b[1]));
}

// Split a float4 into tf32 (hi,lo) pairs, store in fragment order (2x STS.128).
__device__ __forceinline__ void split_store(float2* p, float4 g) {
    float h0 = __uint_as_float(f2tf32(g.x)); float l0 = g.x - h0;
    float h1 = __uint_as_float(f2tf32(g.y)); float l1 = g.y - h1;
    float h2 = __uint_as_float(f2tf32(g.z)); float l2 = g.z - h2;
    float h3 = __uint_as_float(f2tf32(g.w)); float l3 = g.w - h3;
    *(float4*)(p)     = make_float4(h0, l0, h1, l1);
    *(float4*)(p + 2) = make_float4(h2, l2, h3, l3);
}

// ===========================================================================
// 3xTF32 mma.sync GEMM, double-buffered, HIGH-OCCUPANCY (R7 change):
// 512 threads = 16 warps in a 4x4 grid, each owning a 32m x 32n warp tile
// (2x4 m16n8 mma tiles). Per-thread regs ~105 (acc 32 + frags 32 + prefetch
// 16) so 16 warps fit the 64K regfile -> 4 warps/SMSP (R6 had 2, which left
// the tensor pipe idle 72%: LDS/HMMA latency uncovered).
// CTA tile 128x128, BK=32, two 64KB smem stages (fragment-major interleaved
// (hi,lo) float2 — layout identical to R5/R6, verified correct).
// Fragment mapping (CUTLASS SM80_16x8x8_F32TF32TF32F32_TN).
// EPI==0: scatter to g_q/g_k/g_v.  EPI==1: A=g_ctx, out = C + bias.
// ===========================================================================
#define GEMM_STAGE_BYTES 65536
#define GEMM_SMEM_BYTES  (2*GEMM_STAGE_BYTES)   // 128 KB

template<int EPI>
__global__ __launch_bounds__(512) void mma_gemm_kernel(
    const float* __restrict__ Ain,
    const float* __restrict__ W,
    const float* __restrict__ bias,
    float* __restrict__ out,
    int K, int Nfull)
{
    extern __shared__ char dsmem[];
    const float* A = (EPI == 1) ? (const float*)g_ctx : Ain;

    const int tid  = threadIdx.x;
    const int wid  = tid >> 5;
    const int lane = tid & 31;
    const int wm   = wid & 3;      // 4 row groups of 32
    const int wn   = wid >> 2;     // 4 col groups of 32
    const int gr   = lane >> 2;
    const int tg   = lane & 3;
    const int m0   = blockIdx.y * 128;
    const int n0   = blockIdx.x * 128;

    // ---- per-thread fill slots: 2 float4 loads each for A and B ----
    const float *pA[2], *pB[2];
    int offA[2], offB[2];     // float2 indices within a stage
    #pragma unroll
    for (int t = 0; t < 2; t++) {
        int idx = tid + t * 512;     // 0..1023
        int row = idx >> 3;          // 0..127
        int c4  = idx & 7;           // 16B column within BK=32
        pA[t] = A + (size_t)(m0 + row) * K + c4 * 4;
        pB[t] = W + (size_t)(n0 + row) * K + c4 * 4;
        int kk   = c4 >> 1;
        int mt   = row >> 4;
        int aidx = ((row >> 3) & 1) | ((c4 & 1) << 1);
        offA[t]  = (((kk*8 + mt)*4 + aidx) << 5) + (row & 7) * 4;
        int nt   = row >> 3;
        int bidx = c4 & 1;
        offB[t]  = (((kk*16 + nt)*2 + bidx) << 5) + (row & 7) * 4;
    }

    float acc[2][4][4];
    #pragma unroll
    for (int i = 0; i < 2; i++)
        #pragma unroll
        for (int j = 0; j < 4; j++)
            #pragma unroll
            for (int v = 0; v < 4; v++) acc[i][j][v] = 0.f;

    // ---- prologue: load + fill stage 0 ----
    float4 gA[2], gB[2];
    #pragma unroll
    for (int t = 0; t < 2; t++) {
        gA[t] = *(const float4*)(pA[t]);
        gB[t] = *(const float4*)(pB[t]);
    }
    {
        float2* sA0 = (float2*)(dsmem);
        float2* sB0 = (float2*)(dsmem + 32768);
        #pragma unroll
        for (int t = 0; t < 2; t++) {
            split_store(sA0 + offA[t], gA[t]);
            split_store(sB0 + offB[t], gB[t]);
        }
    }
    __syncthreads();

    const int niter = K >> 5;   // BK = 32
    for (int it = 0; it < niter; it++) {
        const int p = it & 1;
        float2* cA = (float2*)(dsmem + p*GEMM_STAGE_BYTES);
        float2* cB = (float2*)(dsmem + p*GEMM_STAGE_BYTES + 32768);
        const bool more = (it + 1 < niter);

        // prefetch next slab into registers (covered by the MMA block below)
        if (more) {
            const int ko = (it + 1) << 5;
            #pragma unroll
            for (int t = 0; t < 2; t++) {
                gA[t] = *(const float4*)(pA[t] + ko);
                gB[t] = *(const float4*)(pB[t] + ko);
            }
        }

        // ---- mma over the 4 k8-steps of this stage ----
        #pragma unroll
        for (int kk = 0; kk < 4; kk++) {
            uint32_t ah[2][4], al[2][4], bh[4][2], bl[4][2];
            #pragma unroll
            for (int mt4 = 0; mt4 < 2; mt4++) {
                int mt = wm*2 + mt4;
                #pragma unroll
                for (int ai = 0; ai < 4; ai++) {
                    float2 v = cA[(((kk*8 + mt)*4 + ai) << 5) + lane];
                    ah[mt4][ai] = __float_as_uint(v.x);
                    al[mt4][ai] = __float_as_uint(v.y);
                }
            }
            #pragma unroll
            for (int nt4 = 0; nt4 < 4; nt4++) {
                int nt = wn*4 + nt4;
                #pragma unroll
                for (int bi = 0; bi < 2; bi++) {
                    float2 v = cB[(((kk*16 + nt)*2 + bi) << 5) + lane];
                    bh[nt4][bi] = __float_as_uint(v.x);
                    bl[nt4][bi] = __float_as_uint(v.y);
                }
            }
            // 3 passes; 8 independent mmas per pass
            #pragma unroll
            for (int mt4 = 0; mt4 < 2; mt4++)
                #pragma unroll
                for (int nt4 = 0; nt4 < 4; nt4++)
                    mma8(acc[mt4][nt4], ah[mt4], bh[nt4]);
            #pragma unroll
            for (int mt4 = 0; mt4 < 2; mt4++)
                #pragma unroll
                for (int nt4 = 0; nt4 < 4; nt4++)
                    mma8(acc[mt4][nt4], ah[mt4], bl[nt4]);
            #pragma unroll
            for (int mt4 = 0; mt4 < 2; mt4++)
                #pragma unroll
                for (int nt4 = 0; nt4 < 4; nt4++)
                    mma8(acc[mt4][nt4], al[mt4], bh[nt4]);
        }

        // ---- fill the other stage (read by mma at it+1) ----
        if (more) {
            float2* nA = (float2*)(dsmem + (p^1)*GEMM_STAGE_BYTES);
            float2* nB = (float2*)(dsmem + (p^1)*GEMM_STAGE_BYTES + 32768);
            #pragma unroll
            for (int t = 0; t < 2; t++) {
                split_store(nA + offA[t], gA[t]);
                split_store(nB + offB[t], gB[t]);
            }
        }
        __syncthreads();
    }

    // ---- epilogue ----
    #pragma unroll
    for (int mt4 = 0; mt4 < 2; mt4++) {
        const int mlo = m0 + wm*32 + mt4*16 + gr;
        const int mhi = mlo + 8;
        #pragma unroll
        for (int nt4 = 0; nt4 < 4; nt4++) {
            const int nn = n0 + wn*32 + nt4*8 + tg*2;
            const float* d = acc[mt4][nt4];
            if (EPI == 0) {
                const int which = n0 >> 10;
                float* dst = (which == 0) ? g_q : ((which == 1) ? g_k : g_v);
                const int nl = nn & 1023;
                const int h  = nl >> 6;
                const int dd = nl & (HDIM - 1);
                {
                    int b = mlo >> 11, s = mlo & (SEQ - 1);
                    *(float2*)&dst[(((b*NHEAD + h)*SEQ) + s)*HDIM + dd] =
                        make_float2(d[0], d[1]);
                }
                {
                    int b = mhi >> 11, s = mhi & (SEQ - 1);
                    *(float2*)&dst[(((b*NHEAD + h)*SEQ) + s)*HDIM + dd] =
                        make_float2(d[2], d[3]);
                }
            } else {
                float2 bv = *(const float2*)&bias[nn];
                *(float2*)&out[(size_t)mlo * Nfull + nn] =
                    make_float2(d[0] + bv.x, d[1] + bv.y);
                *(float2*)&out[(size_t)mhi * Nfull + nn] =
                    make_float2(d[2] + bv.x, d[3] + bv.y);
            }
        }
    }
}

// ---------------------------------------------------------------------------
// Causal flash attention, fp32, D=64, register-blocked (unchanged from R3:
// measured ~640us; 4x4 micro-tile, 16 FMA per 8 LDS).
// ---------------------------------------------------------------------------
__global__ __launch_bounds__(256) void flash_kernel()
{
    __shared__ __align__(16) float Qs[64][65];
    __shared__ __align__(16) float Ks[64][65];
    __shared__ __align__(16) float Vs[64][68];
    __shared__ __align__(16) float Ps[64][68];

    const int qt = blockIdx.x;
    const int h  = blockIdx.y;
    const int b  = blockIdx.z;
    const int bh = b*NHEAD + h;
    const float* Qg = g_q + (size_t)bh * SEQ * HDIM;
    const float* Kg = g_k + (size_t)bh * SEQ * HDIM;
    const float* Vg = g_v + (size_t)bh * SEQ * HDIM;

    const int tid = threadIdx.x;
    const int ty  = tid >> 4;
    const int tx  = tid & 15;
    const int r0  = ty * 4;
    const int c0  = tx * 4;
    const int q0  = qt * 64;

    for (int i = tid; i < 64*16; i += 256) {
        int rr = i >> 4, ff = (i & 15) << 2;
        float4 v = *(const float4*)(Qg + (size_t)(q0 + rr)*HDIM + ff);
        Qs[rr][ff+0] = v.x*8.f; Qs[rr][ff+1] = v.y*8.f;
        Qs[rr][ff+2] = v.z*8.f; Qs[rr][ff+3] = v.w*8.f;
    }

    float m[4], l[4], acc[4][4];
    #pragma unroll
    for (int i = 0; i < 4; i++) {
        m[i] = -1e30f; l[i] = 0.f;
        #pragma unroll
        for (int j = 0; j < 4; j++) acc[i][j] = 0.f;
    }

    for (int kt = 0; kt <= qt; kt++) {
        __syncthreads();
        for (int i = tid; i < 64*16; i += 256) {
            int rr = i >> 4, ff = (i & 15) << 2;
            float4 kv = *(const float4*)(Kg + (size_t)(kt*64 + rr)*HDIM + ff);
            float4 vv = *(const float4*)(Vg + (size_t)(kt*64 + rr)*HDIM + ff);
            Ks[rr][ff+0] = kv.x; Ks[rr][ff+1] = kv.y;
            Ks[rr][ff+2] = kv.z; Ks[rr][ff+3] = kv.w;
            *(float4*)&Vs[rr][ff] = vv;
        }
        __syncthreads();

        float s[4][4];
        #pragma unroll
        for (int i = 0; i < 4; i++)
            #pragma unroll
            for (int j = 0; j < 4; j++) s[i][j] = 0.f;

        #pragma unroll 8
        for (int d = 0; d < 64; d++) {
            float qf[4], kf[4];
            #pragma unroll
            for (int i = 0; i < 4; i++) qf[i] = Qs[r0+i][d];
            #pragma unroll
            for (int j = 0; j < 4; j++) kf[j] = Ks[c0+j][d];
            #pragma unroll
            for (int i = 0; i < 4; i++)
                #pragma unroll
                for (int j = 0; j < 4; j++)
                    s[i][j] = fmaf(qf[i], kf[j], s[i][j]);
        }

        if (kt == qt) {
            #pragma unroll
            for (int i = 0; i < 4; i++)
                #pragma unroll
                for (int j = 0; j < 4; j++)
                    if (c0 + j > r0 + i) s[i][j] = -1e30f;
        }

        float mnew[4], rsum[4];
        #pragma unroll
        for (int i = 0; i < 4; i++) {
            float mloc = fmaxf(fmaxf(s[i][0], s[i][1]), fmaxf(s[i][2], s[i][3]));
            mloc = fmaxf(mloc, __shfl_xor_sync(0xffffffffu, mloc, 1));
            mloc = fmaxf(mloc, __shfl_xor_sync(0xffffffffu, mloc, 2));
            mloc = fmaxf(mloc, __shfl_xor_sync(0xffffffffu, mloc, 4));
            mloc = fmaxf(mloc, __shfl_xor_sync(0xffffffffu, mloc, 8));
            mnew[i] = fmaxf(m[i], mloc);
        }
        #pragma unroll
        for (int i = 0; i < 4; i++) {
            float rs = 0.f;
            #pragma unroll
            for (int j = 0; j < 4; j++) {
                float e = __expf(s[i][j] - mnew[i]);
                s[i][j] = e;
                rs += e;
            }
            rs += __shfl_xor_sync(0xffffffffu, rs, 1);
            rs += __shfl_xor_sync(0xffffffffu, rs, 2);
            rs += __shfl_xor_sync(0xffffffffu, rs, 4);
            rs += __shfl_xor_sync(0xffffffffu, rs, 8);
            rsum[i] = rs;
        }
        #pragma unroll
        for (int i = 0; i < 4; i++) {
            float alpha = __expf(m[i] - mnew[i]);
            m[i] = mnew[i];
            l[i] = l[i] * alpha + rsum[i];
            #pragma unroll
            for (int j = 0; j < 4; j++) acc[i][j] *= alpha;
            *(float4*)&Ps[r0+i][c0] = make_float4(s[i][0], s[i][1], s[i][2], s[i][3]);
        }
        __syncthreads();

        #pragma unroll 8
        for (int k = 0; k < 64; k++) {
            float pf[4];
            #pragma unroll
            for (int i = 0; i < 4; i++) pf[i] = Ps[r0+i][k];
            float4 v = *(const float4*)&Vs[k][c0];
            #pragma unroll
            for (int i = 0; i < 4; i++) {
                acc[i][0] = fmaf(pf[i], v.x, acc[i][0]);
                acc[i][1] = fmaf(pf[i], v.y, acc[i][1]);
                acc[i][2] = fmaf(pf[i], v.z, acc[i][2]);
                acc[i][3] = fmaf(pf[i], v.w, acc[i][3]);
            }
        }
    }

    #pragma unroll
    for (int i = 0; i < 4; i++) {
        float inv = 1.0f / l[i];
        float* outp = g_ctx + ((size_t)(b*SEQ + q0 + r0 + i)) * EMB + h*HDIM + c0;
        *(float4*)outp = make_float4(acc[i][0]*inv, acc[i][1]*inv,
                                     acc[i][2]*inv, acc[i][3]*inv);
    }
}

// ---------------------------------------------------------------------------
// Inputs (metadata order): x [2,2048,1024] f32, w_qkv [3072,1024] f32,
// w_proj [1024,1024] f32, b_proj [1024] f32. Output: [2,2048,1024] f32.
// ---------------------------------------------------------------------------
extern "C" void kernel_launch(void* const* d_in, const int* in_sizes, int n_in,
                              void* d_out, int out_size)
{
    (void)in_sizes; (void)n_in; (void)out_size;
    const float* x      = (const float*)d_in[0];
    const float* w_qkv  = (const float*)d_in[1];
    const float* w_proj = (const float*)d_in[2];
    const float* b_proj = (const float*)d_in[3];
    float* out = (float*)d_out;

    cudaFuncSetAttribute(mma_gemm_kernel<0>,
                         cudaFuncAttributeMaxDynamicSharedMemorySize, GEMM_SMEM_BYTES);
    cudaFuncSetAttribute(mma_gemm_kernel<1>,
                         cudaFuncAttributeMaxDynamicSharedMemorySize, GEMM_SMEM_BYTES);

    // 1) QKV GEMM (3xTF32 mma.sync): [4096,1024] @ [3072,1024]^T -> g_q/g_k/g_v
    dim3 g1((3*EMB)/128, MTOT/128);
    mma_gemm_kernel<0><<<g1, 512, GEMM_SMEM_BYTES>>>(x, w_qkv, nullptr, nullptr,
                                                     EMB, 3*EMB);

    // 2) Causal flash attention -> g_ctx
    dim3 g2(SEQ/64, NHEAD, BATCH);
    flash_kernel<<<g2, 256>>>();

    // 3) Proj GEMM + bias (3xTF32 mma.sync): g_ctx @ w_proj^T + b_proj -> out
    dim3 g3(EMB/128, MTOT/128);
    mma_gemm_kernel<1><<<g3, 512, GEMM_SMEM_BYTES>>>(nullptr, w_proj, b_proj, out,
                                                     EMB, EMB);
}

// round 9
// speedup vs baseline: 1.7141x; 1.6149x over previous
#include <cuda_runtime.h>
#include <cuda_fp16.h>
#include <math.h>
#include <stdint.h>

#define BATCH 2
#define SEQ   2048
#define EMB   1024
#define NHEAD 16
#define HDIM  64
#define MTOT  (BATCH*SEQ)   // 4096

// Scratch (allocation-free contract: __device__ globals)
__device__ float g_q[BATCH*NHEAD*SEQ*HDIM];   // [b][h][s][d]
__device__ float g_k[BATCH*NHEAD*SEQ*HDIM];
__device__ float g_v[BATCH*NHEAD*SEQ*HDIM];
__device__ float g_ctx[(size_t)MTOT*EMB];     // [b*s][e]

// ===========================================================================
// m16n8k16 fp16 mma.sync with fp32 accumulate (sm_80+ PTX; tcgen05 is
// unreachable — harness builds compute_103 PTX). 2048 MAC/instr = 2x the
// tf32 k8 path; tensor busy time was the constant across R5-R7, so halving
// instruction count is the lever that actually cuts the floor.
// ===========================================================================
__device__ __forceinline__ void mma16(float* d, const uint32_t* a, const uint32_t* b) {
    asm volatile(
        "mma.sync.aligned.m16n8k16.row.col.f32.f16.f16.f32 "
        "{%0,%1,%2,%3}, {%4,%5,%6,%7}, {%8,%9}, {%0,%1,%2,%3};"
        : "+f"(d[0]), "+f"(d[1]), "+f"(d[2]), "+f"(d[3])
        : "r"(a[0]), "r"(a[1]), "r"(a[2]), "r"(a[3]), "r"(b[0]), "r"(b[1]));
}

// Split float4 into fp16 (hi, lo) pair-packed b32 words:
// returns {hi(k0,k1), lo(k0,k1), hi(k2,k3), lo(k2,k3)}.
__device__ __forceinline__ uint4 split4(float4 g) {
    __half2 h01 = __floats2half2_rn(g.x, g.y);
    __half2 h23 = __floats2half2_rn(g.z, g.w);
    float2 f01 = __half22float2(h01);
    float2 f23 = __half22float2(h23);
    __half2 l01 = __floats2half2_rn(g.x - f01.x, g.y - f01.y);
    __half2 l23 = __floats2half2_rn(g.z - f23.x, g.w - f23.y);
    uint4 r;
    r.x = *reinterpret_cast<uint32_t*>(&h01);
    r.y = *reinterpret_cast<uint32_t*>(&l01);
    r.z = *reinterpret_cast<uint32_t*>(&h23);
    r.w = *reinterpret_cast<uint32_t*>(&l23);
    return r;
}

// ===========================================================================
// 3xFP16 mma.sync GEMM, double-buffered: C[M,N] = A[M,K] @ W[N,K]^T.
// CTA tile 128x128, BK=32 (= 2 k16 steps), 512 threads = 16 warps (4x4),
// warp tile 32m x 32n = 2x4 m16n8 tiles. 3 passes (hh, hl, lh; lo*lo
// dropped, per-product error ~2^-21).
// Smem: fragment-major uint2 = (hi_pair, lo_pair); one LDS.64 fetches a
// fragment reg AND its lo counterpart. Stage = 32KB (A 16K + B 16K), x2.
// Fragment mapping (PTX m16n8k16.row.col):
//   A: a0=(gr,2tg) a1=(gr+8,2tg) a2=(gr,2tg+8) a3=(gr+8,2tg+8)  [pairs k,k+1]
//   B: b0=(k=2tg,n=gr) b1=(k=2tg+8,n=gr)                         [pairs]
//   D: d0=(gr,2tg) d1=(gr,2tg+1) d2=(gr+8,2tg) d3=(gr+8,2tg+1)
// EPI==0: scatter to g_q/g_k/g_v.  EPI==1: A=g_ctx, out = C + bias.
// ===========================================================================
#define GEMM_STAGE_BYTES 32768
#define GEMM_SMEM_BYTES  (2*GEMM_STAGE_BYTES)   // 64 KB

template<int EPI>
__global__ __launch_bounds__(512) void mma_gemm_kernel(
    const float* __restrict__ Ain,
    const float* __restrict__ W,
    const float* __restrict__ bias,
    float* __restrict__ out,
    int K, int Nfull)
{
    extern __shared__ char dsmem[];
    const float* A = (EPI == 1) ? (const float*)g_ctx : Ain;

    const int tid  = threadIdx.x;
    const int wid  = tid >> 5;
    const int lane = tid & 31;
    const int wm   = wid & 3;      // 4 row groups of 32
    const int wn   = wid >> 2;     // 4 col groups of 32
    const int gr   = lane >> 2;
    const int tg   = lane & 3;
    const int m0   = blockIdx.y * 128;
    const int n0   = blockIdx.x * 128;

    // ---- per-thread fill slots: 2 float4 loads each for A and B ----
    // slot -> fragment-major smem offset (uint2 units within a stage)
    const float *pA[2], *pB[2];
    int offA[2], offB[2];
    #pragma unroll
    for (int t = 0; t < 2; t++) {
        int idx = tid + t * 512;     // 0..1023
        int row = idx >> 3;          // 0..127
        int c4  = idx & 7;           // float4 column within BK=32
        pA[t] = A + (size_t)(m0 + row) * K + c4 * 4;
        pB[t] = W + (size_t)(n0 + row) * K + c4 * 4;
        int kk  = c4 >> 2;           // k16 step (0/1)
        int kw4 = c4 & 3;            // float4 within the k16 step
        int aih = kw4 >> 1;          // high-k half selector (ai bit1 / bi)
        int tg0 = (kw4 & 1) * 2;     // first tg covered (even)
        // A: [kk][mt 0..7][ai 0..3][lane]
        int mt = row >> 4, rw = row & 15;
        int ai = (rw >> 3) | (aih << 1);
        offA[t] = (((kk*8 + mt)*4 + ai) << 5) + (rw & 7)*4 + tg0;
        // B: [kk][nt 0..15][bi 0..1][lane]
        int nt = row >> 3;
        offB[t] = (((kk*16 + nt)*2 + aih) << 5) + (row & 7)*4 + tg0;
    }

    float acc[2][4][4];
    #pragma unroll
    for (int i = 0; i < 2; i++)
        #pragma unroll
        for (int j = 0; j < 4; j++)
            #pragma unroll
            for (int v = 0; v < 4; v++) acc[i][j][v] = 0.f;

    // ---- prologue: load + fill stage 0 ----
    float4 gA[2], gB[2];
    #pragma unroll
    for (int t = 0; t < 2; t++) {
        gA[t] = *(const float4*)(pA[t]);
        gB[t] = *(const float4*)(pB[t]);
    }
    {
        uint2* sA0 = (uint2*)(dsmem);
        uint2* sB0 = (uint2*)(dsmem + 16384);
        #pragma unroll
        for (int t = 0; t < 2; t++) {
            *(uint4*)(sA0 + offA[t]) = split4(gA[t]);
            *(uint4*)(sB0 + offB[t]) = split4(gB[t]);
        }
    }
    __syncthreads();

    const int niter = K >> 5;   // BK = 32
    for (int it = 0; it < niter; it++) {
        const int p = it & 1;
        uint2* cA = (uint2*)(dsmem + p*GEMM_STAGE_BYTES);
        uint2* cB = (uint2*)(dsmem + p*GEMM_STAGE_BYTES + 16384);
        const bool more = (it + 1 < niter);

        // prefetch next slab into registers (covered by the MMA block below)
        if (more) {
            const int ko = (it + 1) << 5;
            #pragma unroll
            for (int t = 0; t < 2; t++) {
                gA[t] = *(const float4*)(pA[t] + ko);
                gB[t] = *(const float4*)(pB[t] + ko);
            }
        }

        // ---- mma over the 2 k16-steps of this stage ----
        #pragma unroll
        for (int kk = 0; kk < 2; kk++) {
            uint32_t ah[2][4], al[2][4], bh[4][2], bl[4][2];
            #pragma unroll
            for (int mt4 = 0; mt4 < 2; mt4++) {
                int mt = wm*2 + mt4;
                #pragma unroll
                for (int ai = 0; ai < 4; ai++) {
                    uint2 v = cA[(((kk*8 + mt)*4 + ai) << 5) + lane];
                    ah[mt4][ai] = v.x;
                    al[mt4][ai] = v.y;
                }
            }
            #pragma unroll
            for (int nt4 = 0; nt4 < 4; nt4++) {
                int nt = wn*4 + nt4;
                #pragma unroll
                for (int bi = 0; bi < 2; bi++) {
                    uint2 v = cB[(((kk*16 + nt)*2 + bi) << 5) + lane];
                    bh[nt4][bi] = v.x;
                    bl[nt4][bi] = v.y;
                }
            }
            // 3 passes; 8 independent mmas per pass
            #pragma unroll
            for (int mt4 = 0; mt4 < 2; mt4++)
                #pragma unroll
                for (int nt4 = 0; nt4 < 4; nt4++)
                    mma16(acc[mt4][nt4], ah[mt4], bh[nt4]);
            #pragma unroll
            for (int mt4 = 0; mt4 < 2; mt4++)
                #pragma unroll
                for (int nt4 = 0; nt4 < 4; nt4++)
                    mma16(acc[mt4][nt4], ah[mt4], bl[nt4]);
            #pragma unroll
            for (int mt4 = 0; mt4 < 2; mt4++)
                #pragma unroll
                for (int nt4 = 0; nt4 < 4; nt4++)
                    mma16(acc[mt4][nt4], al[mt4], bh[nt4]);
        }

        // ---- fill the other stage (read by mma at it+1) ----
        if (more) {
            uint2* nA = (uint2*)(dsmem + (p^1)*GEMM_STAGE_BYTES);
            uint2* nB = (uint2*)(dsmem + (p^1)*GEMM_STAGE_BYTES + 16384);
            #pragma unroll
            for (int t = 0; t < 2; t++) {
                *(uint4*)(nA + offA[t]) = split4(gA[t]);
                *(uint4*)(nB + offB[t]) = split4(gB[t]);
            }
        }
        __syncthreads();
    }

    // ---- epilogue ----
    #pragma unroll
    for (int mt4 = 0; mt4 < 2; mt4++) {
        const int mlo = m0 + wm*32 + mt4*16 + gr;
        const int mhi = mlo + 8;
        #pragma unroll
        for (int nt4 = 0; nt4 < 4; nt4++) {
            const int nn = n0 + wn*32 + nt4*8 + tg*2;
            const float* d = acc[mt4][nt4];
            if (EPI == 0) {
                const int which = n0 >> 10;
                float* dst = (which == 0) ? g_q : ((which == 1) ? g_k : g_v);
                const int nl = nn & 1023;
                const int h  = nl >> 6;
                const int dd = nl & (HDIM - 1);
                {
                    int b = mlo >> 11, s = mlo & (SEQ - 1);
                    *(float2*)&dst[(((b*NHEAD + h)*SEQ) + s)*HDIM + dd] =
                        make_float2(d[0], d[1]);
                }
                {
                    int b = mhi >> 11, s = mhi & (SEQ - 1);
                    *(float2*)&dst[(((b*NHEAD + h)*SEQ) + s)*HDIM + dd] =
                        make_float2(d[2], d[3]);
                }
            } else {
                float2 bv = *(const float2*)&bias[nn];
                *(float2*)&out[(size_t)mlo * Nfull + nn] =
                    make_float2(d[0] + bv.x, d[1] + bv.y);
                *(float2*)&out[(size_t)mhi * Nfull + nn] =
                    make_float2(d[2] + bv.x, d[3] + bv.y);
            }
        }
    }
}

// ---------------------------------------------------------------------------
// Causal flash attention, fp32, D=64, register-blocked (unchanged from R3:
// measured ~640us; 4x4 micro-tile, 16 FMA per 8 LDS).
// ---------------------------------------------------------------------------
__global__ __launch_bounds__(256) void flash_kernel()
{
    __shared__ __align__(16) float Qs[64][65];
    __shared__ __align__(16) float Ks[64][65];
    __shared__ __align__(16) float Vs[64][68];
    __shared__ __align__(16) float Ps[64][68];

    const int qt = blockIdx.x;
    const int h  = blockIdx.y;
    const int b  = blockIdx.z;
    const int bh = b*NHEAD + h;
    const float* Qg = g_q + (size_t)bh * SEQ * HDIM;
    const float* Kg = g_k + (size_t)bh * SEQ * HDIM;
    const float* Vg = g_v + (size_t)bh * SEQ * HDIM;

    const int tid = threadIdx.x;
    const int ty  = tid >> 4;
    const int tx  = tid & 15;
    const int r0  = ty * 4;
    const int c0  = tx * 4;
    const int q0  = qt * 64;

    for (int i = tid; i < 64*16; i += 256) {
        int rr = i >> 4, ff = (i & 15) << 2;
        float4 v = *(const float4*)(Qg + (size_t)(q0 + rr)*HDIM + ff);
        Qs[rr][ff+0] = v.x*8.f; Qs[rr][ff+1] = v.y*8.f;
        Qs[rr][ff+2] = v.z*8.f; Qs[rr][ff+3] = v.w*8.f;
    }

    float m[4], l[4], acc[4][4];
    #pragma unroll
    for (int i = 0; i < 4; i++) {
        m[i] = -1e30f; l[i] = 0.f;
        #pragma unroll
        for (int j = 0; j < 4; j++) acc[i][j] = 0.f;
    }

    for (int kt = 0; kt <= qt; kt++) {
        __syncthreads();
        for (int i = tid; i < 64*16; i += 256) {
            int rr = i >> 4, ff = (i & 15) << 2;
            float4 kv = *(const float4*)(Kg + (size_t)(kt*64 + rr)*HDIM + ff);
            float4 vv = *(const float4*)(Vg + (size_t)(kt*64 + rr)*HDIM + ff);
            Ks[rr][ff+0] = kv.x; Ks[rr][ff+1] = kv.y;
            Ks[rr][ff+2] = kv.z; Ks[rr][ff+3] = kv.w;
            *(float4*)&Vs[rr][ff] = vv;
        }
        __syncthreads();

        float s[4][4];
        #pragma unroll
        for (int i = 0; i < 4; i++)
            #pragma unroll
            for (int j = 0; j < 4; j++) s[i][j] = 0.f;

        #pragma unroll 8
        for (int d = 0; d < 64; d++) {
            float qf[4], kf[4];
            #pragma unroll
            for (int i = 0; i < 4; i++) qf[i] = Qs[r0+i][d];
            #pragma unroll
            for (int j = 0; j < 4; j++) kf[j] = Ks[c0+j][d];
            #pragma unroll
            for (int i = 0; i < 4; i++)
                #pragma unroll
                for (int j = 0; j < 4; j++)
                    s[i][j] = fmaf(qf[i], kf[j], s[i][j]);
        }

        if (kt == qt) {
            #pragma unroll
            for (int i = 0; i < 4; i++)
                #pragma unroll
                for (int j = 0; j < 4; j++)
                    if (c0 + j > r0 + i) s[i][j] = -1e30f;
        }

        float mnew[4], rsum[4];
        #pragma unroll
        for (int i = 0; i < 4; i++) {
            float mloc = fmaxf(fmaxf(s[i][0], s[i][1]), fmaxf(s[i][2], s[i][3]));
            mloc = fmaxf(mloc, __shfl_xor_sync(0xffffffffu, mloc, 1));
            mloc = fmaxf(mloc, __shfl_xor_sync(0xffffffffu, mloc, 2));
            mloc = fmaxf(mloc, __shfl_xor_sync(0xffffffffu, mloc, 4));
            mloc = fmaxf(mloc, __shfl_xor_sync(0xffffffffu, mloc, 8));
            mnew[i] = fmaxf(m[i], mloc);
        }
        #pragma unroll
        for (int i = 0; i < 4; i++) {
            float rs = 0.f;
            #pragma unroll
            for (int j = 0; j < 4; j++) {
                float e = __expf(s[i][j] - mnew[i]);
                s[i][j] = e;
                rs += e;
            }
            rs += __shfl_xor_sync(0xffffffffu, rs, 1);
            rs += __shfl_xor_sync(0xffffffffu, rs, 2);
            rs += __shfl_xor_sync(0xffffffffu, rs, 4);
            rs += __shfl_xor_sync(0xffffffffu, rs, 8);
            rsum[i] = rs;
        }
        #pragma unroll
        for (int i = 0; i < 4; i++) {
            float alpha = __expf(m[i] - mnew[i]);
            m[i] = mnew[i];
            l[i] = l[i] * alpha + rsum[i];
            #pragma unroll
            for (int j = 0; j < 4; j++) acc[i][j] *= alpha;
            *(float4*)&Ps[r0+i][c0] = make_float4(s[i][0], s[i][1], s[i][2], s[i][3]);
        }
        __syncthreads();

        #pragma unroll 8
        for (int k = 0; k < 64; k++) {
            float pf[4];
            #pragma unroll
            for (int i = 0; i < 4; i++) pf[i] = Ps[r0+i][k];
            float4 v = *(const float4*)&Vs[k][c0];
            #pragma unroll
            for (int i = 0; i < 4; i++) {
                acc[i][0] = fmaf(pf[i], v.x, acc[i][0]);
                acc[i][1] = fmaf(pf[i], v.y, acc[i][1]);
                acc[i][2] = fmaf(pf[i], v.z, acc[i][2]);
                acc[i][3] = fmaf(pf[i], v.w, acc[i][3]);
            }
        }
    }

    #pragma unroll
    for (int i = 0; i < 4; i++) {
        float inv = 1.0f / l[i];
        float* outp = g_ctx + ((size_t)(b*SEQ + q0 + r0 + i)) * EMB + h*HDIM + c0;
        *(float4*)outp = make_float4(acc[i][0]*inv, acc[i][1]*inv,
                                     acc[i][2]*inv, acc[i][3]*inv);
    }
}

// ---------------------------------------------------------------------------
// Inputs (metadata order): x [2,2048,1024] f32, w_qkv [3072,1024] f32,
// w_proj [1024,1024] f32, b_proj [1024] f32. Output: [2,2048,1024] f32.
// ---------------------------------------------------------------------------
extern "C" void kernel_launch(void* const* d_in, const int* in_sizes, int n_in,
                              void* d_out, int out_size)
{
    (void)in_sizes; (void)n_in; (void)out_size;
    const float* x      = (const float*)d_in[0];
    const float* w_qkv  = (const float*)d_in[1];
    const float* w_proj = (const float*)d_in[2];
    const float* b_proj = (const float*)d_in[3];
    float* out = (float*)d_out;

    cudaFuncSetAttribute(mma_gemm_kernel<0>,
                         cudaFuncAttributeMaxDynamicSharedMemorySize, GEMM_SMEM_BYTES);
    cudaFuncSetAttribute(mma_gemm_kernel<1>,
                         cudaFuncAttributeMaxDynamicSharedMemorySize, GEMM_SMEM_BYTES);

    // 1) QKV GEMM (3xFP16 mma.sync): [4096,1024] @ [3072,1024]^T -> g_q/g_k/g_v
    dim3 g1((3*EMB)/128, MTOT/128);
    mma_gemm_kernel<0><<<g1, 512, GEMM_SMEM_BYTES>>>(x, w_qkv, nullptr, nullptr,
                                                     EMB, 3*EMB);

    // 2) Causal flash attention -> g_ctx
    dim3 g2(SEQ/64, NHEAD, BATCH);
    flash_kernel<<<g2, 256>>>();

    // 3) Proj GEMM + bias (3xFP16 mma.sync): g_ctx @ w_proj^T + b_proj -> out
    dim3 g3(EMB/128, MTOT/128);
    mma_gemm_kernel<1><<<g3, 512, GEMM_SMEM_BYTES>>>(nullptr, w_proj, b_proj, out,
                                                     EMB, EMB);
}

// round 10
// speedup vs baseline: 2.4779x; 1.4456x over previous
#include <cuda_runtime.h>
#include <cuda_fp16.h>
#include <math.h>
#include <stdint.h>

#define BATCH 2
#define SEQ   2048
#define EMB   1024
#define NHEAD 16
#define HDIM  64
#define MTOT  (BATCH*SEQ)   // 4096

// Scratch (allocation-free contract: __device__ globals)
__device__ float g_q[BATCH*NHEAD*SEQ*HDIM];   // [b][h][s][d]
__device__ float g_k[BATCH*NHEAD*SEQ*HDIM];
__device__ float g_v[BATCH*NHEAD*SEQ*HDIM];
__device__ float g_ctx[(size_t)MTOT*EMB];     // [b*s][e]

// ===========================================================================
// m16n8k16 fp16 mma.sync, fp32 accumulate (sm_80+ PTX; tcgen05 unreachable —
// harness builds compute_103 PTX). Calibrated R8: ~0.5 mma/cyc/SM ceiling.
// ===========================================================================
__device__ __forceinline__ void mma16(float* d, const uint32_t* a, const uint32_t* b) {
    asm volatile(
        "mma.sync.aligned.m16n8k16.row.col.f32.f16.f16.f32 "
        "{%0,%1,%2,%3}, {%4,%5,%6,%7}, {%8,%9}, {%0,%1,%2,%3};"
        : "+f"(d[0]), "+f"(d[1]), "+f"(d[2]), "+f"(d[3])
        : "r"(a[0]), "r"(a[1]), "r"(a[2]), "r"(a[3]), "r"(b[0]), "r"(b[1]));
}

// Split float4 into fp16 (hi, lo) pair-packed b32 words.
__device__ __forceinline__ uint4 split4(float4 g) {
    __half2 h01 = __floats2half2_rn(g.x, g.y);
    __half2 h23 = __floats2half2_rn(g.z, g.w);
    float2 f01 = __half22float2(h01);
    float2 f23 = __half22float2(h23);
    __half2 l01 = __floats2half2_rn(g.x - f01.x, g.y - f01.y);
    __half2 l23 = __floats2half2_rn(g.z - f23.x, g.w - f23.y);
    uint4 r;
    r.x = *reinterpret_cast<uint32_t*>(&h01);
    r.y = *reinterpret_cast<uint32_t*>(&l01);
    r.z = *reinterpret_cast<uint32_t*>(&h23);
    r.w = *reinterpret_cast<uint32_t*>(&l23);
    return r;
}

// Pack two fp32 into fp16 hi-pair + lo-pair b32 words (register-only).
__device__ __forceinline__ void pack_hl(float x, float y, uint32_t& h, uint32_t& l) {
    __half2 hh = __floats2half2_rn(x, y);
    float2 f = __half22float2(hh);
    __half2 ll = __floats2half2_rn(x - f.x, y - f.y);
    h = *reinterpret_cast<uint32_t*>(&hh);
    l = *reinterpret_cast<uint32_t*>(&ll);
}

// ===========================================================================
// 3xFP16 mma.sync GEMM, double-buffered (R8 winner, unchanged).
// ===========================================================================
#define GEMM_STAGE_BYTES 32768
#define GEMM_SMEM_BYTES  (2*GEMM_STAGE_BYTES)   // 64 KB

template<int EPI>
__global__ __launch_bounds__(512) void mma_gemm_kernel(
    const float* __restrict__ Ain,
    const float* __restrict__ W,
    const float* __restrict__ bias,
    float* __restrict__ out,
    int K, int Nfull)
{
    extern __shared__ char dsmem[];
    const float* A = (EPI == 1) ? (const float*)g_ctx : Ain;

    const int tid  = threadIdx.x;
    const int wid  = tid >> 5;
    const int lane = tid & 31;
    const int wm   = wid & 3;
    const int wn   = wid >> 2;
    const int gr   = lane >> 2;
    const int tg   = lane & 3;
    const int m0   = blockIdx.y * 128;
    const int n0   = blockIdx.x * 128;

    const float *pA[2], *pB[2];
    int offA[2], offB[2];
    #pragma unroll
    for (int t = 0; t < 2; t++) {
        int idx = tid + t * 512;
        int row = idx >> 3;
        int c4  = idx & 7;
        pA[t] = A + (size_t)(m0 + row) * K + c4 * 4;
        pB[t] = W + (size_t)(n0 + row) * K + c4 * 4;
        int kk  = c4 >> 2;
        int kw4 = c4 & 3;
        int aih = kw4 >> 1;
        int tg0 = (kw4 & 1) * 2;
        int mt = row >> 4, rw = row & 15;
        int ai = (rw >> 3) | (aih << 1);
        offA[t] = (((kk*8 + mt)*4 + ai) << 5) + (rw & 7)*4 + tg0;
        int nt = row >> 3;
        offB[t] = (((kk*16 + nt)*2 + aih) << 5) + (row & 7)*4 + tg0;
    }

    float acc[2][4][4];
    #pragma unroll
    for (int i = 0; i < 2; i++)
        #pragma unroll
        for (int j = 0; j < 4; j++)
            #pragma unroll
            for (int v = 0; v < 4; v++) acc[i][j][v] = 0.f;

    float4 gA[2], gB[2];
    #pragma unroll
    for (int t = 0; t < 2; t++) {
        gA[t] = *(const float4*)(pA[t]);
        gB[t] = *(const float4*)(pB[t]);
    }
    {
        uint2* sA0 = (uint2*)(dsmem);
        uint2* sB0 = (uint2*)(dsmem + 16384);
        #pragma unroll
        for (int t = 0; t < 2; t++) {
            *(uint4*)(sA0 + offA[t]) = split4(gA[t]);
            *(uint4*)(sB0 + offB[t]) = split4(gB[t]);
        }
    }
    __syncthreads();

    const int niter = K >> 5;
    for (int it = 0; it < niter; it++) {
        const int p = it & 1;
        uint2* cA = (uint2*)(dsmem + p*GEMM_STAGE_BYTES);
        uint2* cB = (uint2*)(dsmem + p*GEMM_STAGE_BYTES + 16384);
        const bool more = (it + 1 < niter);

        if (more) {
            const int ko = (it + 1) << 5;
            #pragma unroll
            for (int t = 0; t < 2; t++) {
                gA[t] = *(const float4*)(pA[t] + ko);
                gB[t] = *(const float4*)(pB[t] + ko);
            }
        }

        #pragma unroll
        for (int kk = 0; kk < 2; kk++) {
            uint32_t ah[2][4], al[2][4], bh[4][2], bl[4][2];
            #pragma unroll
            for (int mt4 = 0; mt4 < 2; mt4++) {
                int mt = wm*2 + mt4;
                #pragma unroll
                for (int ai = 0; ai < 4; ai++) {
                    uint2 v = cA[(((kk*8 + mt)*4 + ai) << 5) + lane];
                    ah[mt4][ai] = v.x;
                    al[mt4][ai] = v.y;
                }
            }
            #pragma unroll
            for (int nt4 = 0; nt4 < 4; nt4++) {
                int nt = wn*4 + nt4;
                #pragma unroll
                for (int bi = 0; bi < 2; bi++) {
                    uint2 v = cB[(((kk*16 + nt)*2 + bi) << 5) + lane];
                    bh[nt4][bi] = v.x;
                    bl[nt4][bi] = v.y;
                }
            }
            #pragma unroll
            for (int mt4 = 0; mt4 < 2; mt4++)
                #pragma unroll
                for (int nt4 = 0; nt4 < 4; nt4++)
                    mma16(acc[mt4][nt4], ah[mt4], bh[nt4]);
            #pragma unroll
            for (int mt4 = 0; mt4 < 2; mt4++)
                #pragma unroll
                for (int nt4 = 0; nt4 < 4; nt4++)
                    mma16(acc[mt4][nt4], ah[mt4], bl[nt4]);
            #pragma unroll
            for (int mt4 = 0; mt4 < 2; mt4++)
                #pragma unroll
                for (int nt4 = 0; nt4 < 4; nt4++)
                    mma16(acc[mt4][nt4], al[mt4], bh[nt4]);
        }

        if (more) {
            uint2* nA = (uint2*)(dsmem + (p^1)*GEMM_STAGE_BYTES);
            uint2* nB = (uint2*)(dsmem + (p^1)*GEMM_STAGE_BYTES + 16384);
            #pragma unroll
            for (int t = 0; t < 2; t++) {
                *(uint4*)(nA + offA[t]) = split4(gA[t]);
                *(uint4*)(nB + offB[t]) = split4(gB[t]);
            }
        }
        __syncthreads();
    }

    #pragma unroll
    for (int mt4 = 0; mt4 < 2; mt4++) {
        const int mlo = m0 + wm*32 + mt4*16 + gr;
        const int mhi = mlo + 8;
        #pragma unroll
        for (int nt4 = 0; nt4 < 4; nt4++) {
            const int nn = n0 + wn*32 + nt4*8 + tg*2;
            const float* d = acc[mt4][nt4];
            if (EPI == 0) {
                const int which = n0 >> 10;
                float* dst = (which == 0) ? g_q : ((which == 1) ? g_k : g_v);
                const int nl = nn & 1023;
                const int h  = nl >> 6;
                const int dd = nl & (HDIM - 1);
                {
                    int b = mlo >> 11, s = mlo & (SEQ - 1);
                    *(float2*)&dst[(((b*NHEAD + h)*SEQ) + s)*HDIM + dd] =
                        make_float2(d[0], d[1]);
                }
                {
                    int b = mhi >> 11, s = mhi & (SEQ - 1);
                    *(float2*)&dst[(((b*NHEAD + h)*SEQ) + s)*HDIM + dd] =
                        make_float2(d[2], d[3]);
                }
            } else {
                float2 bv = *(const float2*)&bias[nn];
                *(float2*)&out[(size_t)mlo * Nfull + nn] =
                    make_float2(d[0] + bv.x, d[1] + bv.y);
                *(float2*)&out[(size_t)mhi * Nfull + nn] =
                    make_float2(d[2] + bv.x, d[3] + bv.y);
            }
        }
    }
}

// ===========================================================================
// Causal flash attention on tensor cores (3xFP16, m16n8k16). R9 change.
// Block = (qt, h, b): q-tile 128 rows, kv-tile 64 keys, 256 threads = 8
// warps; warp w owns q rows q0+16w .. +15.
// smem (64KB dynamic): Q frags [kk4][mt8][ai4][lane] uint2(hi,lo) = 32KB
// (filled once, x8 scale folded), K frags [kk4][nt8][bi2][lane] = 16KB,
// V frags [kkv4][ntd8][bi2][lane^sw] = 16KB (key-pair transposed fill).
// S accumulator (gr,2tg|2tg+1) IS the A-fragment k-pair layout for PV, so
// P converts fp32->fp16(hi,lo) in registers — no smem round-trip.
// Both QK^T and PV use 3 passes (hh+hl+lh): plain fp16 PV (~5e-4) is too
// close to the 1e-3 gate. Reference scale sqrt(D)=8 folded into Q.
// ===========================================================================
#define FLASH_SMEM_BYTES 65536

__global__ __launch_bounds__(256) void flash_mma_kernel()
{
    extern __shared__ char fsm[];
    uint2* sQ = (uint2*)(fsm);             // 4096 uint2
    uint2* sK = (uint2*)(fsm + 32768);     // 2048 uint2
    uint2* sV = (uint2*)(fsm + 49152);     // 2048 uint2

    const int qt = blockIdx.x;
    const int h  = blockIdx.y;
    const int b  = blockIdx.z;
    const int bh = b*NHEAD + h;
    const float* Qg = g_q + (size_t)bh * SEQ * HDIM;
    const float* Kg = g_k + (size_t)bh * SEQ * HDIM;
    const float* Vg = g_v + (size_t)bh * SEQ * HDIM;

    const int tid  = threadIdx.x;
    const int w    = tid >> 5;
    const int lane = tid & 31;
    const int gr   = lane >> 2;
    const int tg   = lane & 3;
    const int q0   = qt * 128;

    // ---- fill Q fragments once (x8 scale folded) ----
    #pragma unroll
    for (int t = 0; t < 8; t++) {
        int idx = tid + t * 256;       // 0..2047 float4 slots
        int row = idx >> 4;            // 0..127
        int c4  = idx & 15;
        float4 v = *(const float4*)(Qg + (size_t)(q0 + row)*HDIM + c4*4);
        v.x *= 8.f; v.y *= 8.f; v.z *= 8.f; v.w *= 8.f;
        int kk  = c4 >> 2;
        int kw4 = c4 & 3;
        int aih = kw4 >> 1;
        int tg0 = (kw4 & 1) * 2;
        int mt = row >> 4, rw = row & 15;
        int ai = (rw >> 3) | (aih << 1);
        *(uint4*)(sQ + (((kk*8 + mt)*4 + ai) << 5) + (rw & 7)*4 + tg0) = split4(v);
    }

    float m0 = -1e30f, m1 = -1e30f, l0 = 0.f, l1 = 0.f;
    float cacc[8][4];
    #pragma unroll
    for (int nt = 0; nt < 8; nt++)
        #pragma unroll
        for (int v = 0; v < 4; v++) cacc[nt][v] = 0.f;

    const int qrow0 = q0 + 16*w + gr;   // thread's low row
    const int nkt   = 2*qt + 2;         // causal kv-tile count

    for (int kt = 0; kt < nkt; kt++) {
        const int k0 = kt * 64;
        __syncthreads();   // previous iteration's mma reads complete

        // ---- fill K fragments: B-operand (k=d, n=key) ----
        #pragma unroll
        for (int t = 0; t < 4; t++) {
            int idx = tid + t * 256;   // 0..1023
            int row = idx >> 4;        // key 0..63
            int c4  = idx & 15;
            float4 v = *(const float4*)(Kg + (size_t)(k0 + row)*HDIM + c4*4);
            int kk  = c4 >> 2;
            int kw4 = c4 & 3;
            int bi  = kw4 >> 1;
            int tg0 = (kw4 & 1) * 2;
            int nt  = row >> 3;
            *(uint4*)(sK + (((kk*8 + nt)*2 + bi) << 5) + (row & 7)*4 + tg0) = split4(v);
        }

        // ---- fill V fragments: B-operand (k=key, n=d); key-pair transpose ----
        #pragma unroll
        for (int t = 0; t < 2; t++) {
            int idx = tid + t * 256;   // 0..511
            int kp  = idx >> 4;        // key pair 0..31
            int c4  = idx & 15;        // d/4
            float4 v0 = *(const float4*)(Vg + (size_t)(k0 + 2*kp  )*HDIM + c4*4);
            float4 v1 = *(const float4*)(Vg + (size_t)(k0 + 2*kp+1)*HDIM + c4*4);
            int kkv = kp >> 3;
            int tgp = kp & 7;
            int bi  = tgp >> 2;
            int tgv = tgp & 3;
            const float a0[4] = {v0.x, v0.y, v0.z, v0.w};
            const float a1[4] = {v1.x, v1.y, v1.z, v1.w};
            #pragma unroll
            for (int j = 0; j < 4; j++) {
                int d  = c4*4 + j;
                int nt = d >> 3;
                int grv = d & 7;
                uint32_t hh, ll;
                pack_hl(a0[j], a1[j], hh, ll);
                int ln = (grv*4 + tgv) ^ ((nt & 3) << 2);   // bank swizzle
                sV[(((kkv*8 + nt)*2 + bi) << 5) + ln] = make_uint2(hh, ll);
            }
        }
        __syncthreads();

        // warps whose rows are entirely left of this kv tile: skip compute
        if (k0 <= q0 + 16*w + 15) {
            // ---- S = (8q) @ K^T via 3xFP16 ----
            float sacc[8][4];
            #pragma unroll
            for (int nt = 0; nt < 8; nt++)
                #pragma unroll
                for (int v = 0; v < 4; v++) sacc[nt][v] = 0.f;

            #pragma unroll
            for (int kk = 0; kk < 4; kk++) {
                uint32_t qh[4], ql[4], kh[8][2], kl[8][2];
                #pragma unroll
                for (int ai = 0; ai < 4; ai++) {
                    uint2 v = sQ[(((kk*8 + w)*4 + ai) << 5) + lane];
                    qh[ai] = v.x; ql[ai] = v.y;
                }
                #pragma unroll
                for (int nt = 0; nt < 8; nt++)
                    #pragma unroll
                    for (int bi = 0; bi < 2; bi++) {
                        uint2 v = sK[(((kk*8 + nt)*2 + bi) << 5) + lane];
                        kh[nt][bi] = v.x; kl[nt][bi] = v.y;
                    }
                #pragma unroll
                for (int nt = 0; nt < 8; nt++) mma16(sacc[nt], qh, kh[nt]);
                #pragma unroll
                for (int nt = 0; nt < 8; nt++) mma16(sacc[nt], qh, kl[nt]);
                #pragma unroll
                for (int nt = 0; nt < 8; nt++) mma16(sacc[nt], ql, kh[nt]);
            }

            // ---- causal mask (diagonal region only) ----
            if (k0 + 63 > qrow0 || k0 + 63 > qrow0 + 8) {
                #pragma unroll
                for (int nt = 0; nt < 8; nt++) {
                    int c = k0 + nt*8 + 2*tg;
                    if (c     > qrow0    ) sacc[nt][0] = -1e30f;
                    if (c + 1 > qrow0    ) sacc[nt][1] = -1e30f;
                    if (c     > qrow0 + 8) sacc[nt][2] = -1e30f;
                    if (c + 1 > qrow0 + 8) sacc[nt][3] = -1e30f;
                }
            }

            // ---- online softmax (rows gr, gr+8; reduce over 4 tg lanes) ----
            float mx0 = -1e30f, mx1 = -1e30f;
            #pragma unroll
            for (int nt = 0; nt < 8; nt++) {
                mx0 = fmaxf(mx0, fmaxf(sacc[nt][0], sacc[nt][1]));
                mx1 = fmaxf(mx1, fmaxf(sacc[nt][2], sacc[nt][3]));
            }
            mx0 = fmaxf(mx0, __shfl_xor_sync(0xffffffffu, mx0, 1));
            mx0 = fmaxf(mx0, __shfl_xor_sync(0xffffffffu, mx0, 2));
            mx1 = fmaxf(mx1, __shfl_xor_sync(0xffffffffu, mx1, 1));
            mx1 = fmaxf(mx1, __shfl_xor_sync(0xffffffffu, mx1, 2));
            float mn0 = fmaxf(m0, mx0), mn1 = fmaxf(m1, mx1);
            float al0 = __expf(m0 - mn0), al1 = __expf(m1 - mn1);
            m0 = mn0; m1 = mn1;

            float rs0 = 0.f, rs1 = 0.f;
            #pragma unroll
            for (int nt = 0; nt < 8; nt++) {
                sacc[nt][0] = __expf(sacc[nt][0] - mn0); rs0 += sacc[nt][0];
                sacc[nt][1] = __expf(sacc[nt][1] - mn0); rs0 += sacc[nt][1];
                sacc[nt][2] = __expf(sacc[nt][2] - mn1); rs1 += sacc[nt][2];
                sacc[nt][3] = __expf(sacc[nt][3] - mn1); rs1 += sacc[nt][3];
            }
            rs0 += __shfl_xor_sync(0xffffffffu, rs0, 1);
            rs0 += __shfl_xor_sync(0xffffffffu, rs0, 2);
            rs1 += __shfl_xor_sync(0xffffffffu, rs1, 1);
            rs1 += __shfl_xor_sync(0xffffffffu, rs1, 2);
            l0 = l0 * al0 + rs0;
            l1 = l1 * al1 + rs1;

            #pragma unroll
            for (int nt = 0; nt < 8; nt++) {
                cacc[nt][0] *= al0; cacc[nt][1] *= al0;
                cacc[nt][2] *= al1; cacc[nt][3] *= al1;
            }

            // ---- PV: P frags straight from registers; 3xFP16 ----
            #pragma unroll
            for (int kkv = 0; kkv < 4; kkv++) {
                uint32_t ph[4], pl[4], vh[8][2], vl[8][2];
                pack_hl(sacc[2*kkv  ][0], sacc[2*kkv  ][1], ph[0], pl[0]);
                pack_hl(sacc[2*kkv  ][2], sacc[2*kkv  ][3], ph[1], pl[1]);
                pack_hl(sacc[2*kkv+1][0], sacc[2*kkv+1][1], ph[2], pl[2]);
                pack_hl(sacc[2*kkv+1][2], sacc[2*kkv+1][3], ph[3], pl[3]);
                #pragma unroll
                for (int nt = 0; nt < 8; nt++) {
                    int ln = lane ^ ((nt & 3) << 2);
                    #pragma unroll
                    for (int bi = 0; bi < 2; bi++) {
                        uint2 v = sV[(((kkv*8 + nt)*2 + bi) << 5) + ln];
                        vh[nt][bi] = v.x; vl[nt][bi] = v.y;
                    }
                }
                #pragma unroll
                for (int nt = 0; nt < 8; nt++) mma16(cacc[nt], ph, vh[nt]);
                #pragma unroll
                for (int nt = 0; nt < 8; nt++) mma16(cacc[nt], ph, vl[nt]);
                #pragma unroll
                for (int nt = 0; nt < 8; nt++) mma16(cacc[nt], pl, vh[nt]);
            }
        }
    }

    // ---- epilogue: ctx[b][s][h*64+d] = acc / l ----
    const float inv0 = 1.0f / l0;
    const float inv1 = 1.0f / l1;
    float* o0 = g_ctx + ((size_t)(b*SEQ + qrow0    )) * EMB + h*HDIM;
    float* o1 = g_ctx + ((size_t)(b*SEQ + qrow0 + 8)) * EMB + h*HDIM;
    #pragma unroll
    for (int nt = 0; nt < 8; nt++) {
        int d = nt*8 + 2*tg;
        *(float2*)(o0 + d) = make_float2(cacc[nt][0]*inv0, cacc[nt][1]*inv0);
        *(float2*)(o1 + d) = make_float2(cacc[nt][2]*inv1, cacc[nt][3]*inv1);
    }
}

// ---------------------------------------------------------------------------
// Inputs (metadata order): x [2,2048,1024] f32, w_qkv [3072,1024] f32,
// w_proj [1024,1024] f32, b_proj [1024] f32. Output: [2,2048,1024] f32.
// ---------------------------------------------------------------------------
extern "C" void kernel_launch(void* const* d_in, const int* in_sizes, int n_in,
                              void* d_out, int out_size)
{
    (void)in_sizes; (void)n_in; (void)out_size;
    const float* x      = (const float*)d_in[0];
    const float* w_qkv  = (const float*)d_in[1];
    const float* w_proj = (const float*)d_in[2];
    const float* b_proj = (const float*)d_in[3];
    float* out = (float*)d_out;

    cudaFuncSetAttribute(mma_gemm_kernel<0>,
                         cudaFuncAttributeMaxDynamicSharedMemorySize, GEMM_SMEM_BYTES);
    cudaFuncSetAttribute(mma_gemm_kernel<1>,
                         cudaFuncAttributeMaxDynamicSharedMemorySize, GEMM_SMEM_BYTES);
    cudaFuncSetAttribute(flash_mma_kernel,
                         cudaFuncAttributeMaxDynamicSharedMemorySize, FLASH_SMEM_BYTES);

    // 1) QKV GEMM (3xFP16 mma.sync): [4096,1024] @ [3072,1024]^T -> g_q/g_k/g_v
    dim3 g1((3*EMB)/128, MTOT/128);
    mma_gemm_kernel<0><<<g1, 512, GEMM_SMEM_BYTES>>>(x, w_qkv, nullptr, nullptr,
                                                     EMB, 3*EMB);

    // 2) Causal flash attention (3xFP16 mma.sync) -> g_ctx
    dim3 g2(SEQ/128, NHEAD, BATCH);
    flash_mma_kernel<<<g2, 256, FLASH_SMEM_BYTES>>>();

    // 3) Proj GEMM + bias (3xFP16 mma.sync): g_ctx @ w_proj^T + b_proj -> out
    dim3 g3(EMB/128, MTOT/128);
    mma_gemm_kernel<1><<<g3, 512, GEMM_SMEM_BYTES>>>(nullptr, w_proj, b_proj, out,
                                                     EMB, EMB);
}